// round 8
// baseline (speedup 1.0000x reference)
#include <cuda_runtime.h>
#include <cuda_bf16.h>
#include <cstdint>

#define NROWS 50000
#define KNB   32
#define CDIM  128
#define TOPK  16

// ---------------- scratch (device globals; no allocation) ----------------
__device__ __align__(16) float g_M [CDIM * CDIM];     // Wq^T @ Wk
__device__ __align__(16) float g_Ws[CDIM * CDIM];     // triu(W) + triu(W)^T
__device__ __align__(16) float g_scores[(size_t)NROWS * KNB];
__device__ int g_colmask[KNB];
__device__ int g_needfix;
__device__ int g_mask_narrow;   // 1 -> mask elements are 1 byte; 0 -> 4 bytes

// ---------------- cp.async helpers ----------------
__device__ __forceinline__ void cp_async16(void* smem_dst, const void* gptr) {
    uint32_t s = (uint32_t)__cvta_generic_to_shared(smem_dst);
    asm volatile("cp.async.cg.shared.global [%0], [%1], 16;\n" :: "r"(s), "l"(gptr));
}
__device__ __forceinline__ void cp_async_commit() {
    asm volatile("cp.async.commit_group;\n" ::: "memory");
}
template <int N> __device__ __forceinline__ void cp_async_wait() {
    asm volatile("cp.async.wait_group %0;\n" :: "n"(N) : "memory");
}

// ---------------- K0: prep M, Ws, reset flags ----------------
__global__ void prep_kernel(const float* __restrict__ Wq,
                            const float* __restrict__ Wk,
                            const float* __restrict__ W) {
    int c = blockIdx.x;    // 0..127
    int e = threadIdx.x;   // 0..127
    float acc = 0.f;
#pragma unroll 8
    for (int d = 0; d < CDIM; d++)
        acc += Wq[d * CDIM + c] * Wk[d * CDIM + e];
    g_M[c * CDIM + e] = acc;

    float w = (c <= e) ? W[c * CDIM + e] : W[e * CDIM + c];
    g_Ws[c * CDIM + e] = (c == e) ? 2.f * w : w;

    if (c == 0 && e < KNB) g_colmask[e] = 0;
    if (c == 0 && e == KNB) g_needfix = 0;
    if (c == 0 && e == KNB + 1) g_mask_narrow = 0;
}

// ---------------- K0b: sniff knn_mask element width ----------------
__global__ void sniff_kernel(const unsigned int* __restrict__ w) {
    const int nwords = NROWS * KNB / 4;
    int bad = 0;
    for (int i = blockIdx.x * blockDim.x + threadIdx.x; i < nwords;
         i += gridDim.x * blockDim.x) {
        unsigned int v = w[i];
        if (v != 0u && v != 1u && v != 0x3F800000u) bad = 1;
    }
    if (bad) g_mask_narrow = 1;
}

// ---------------- K1: fused projection + streaming kernel ----------------
// 2 rows per 256-thread block (parallel halves, R7 structure). The qM/fW
// projections are computed in-kernel: each thread covers 64 of the 128
// d-values for BOTH rows (halves split d), reading g_M/g_Ws via __ldg
// (L1-resident: identical addresses across all blocks). Projection compute
// overlaps the kf tile cp.async (featS lands in an earlier commit group).
__global__ void __launch_bounds__(256, 5) main_kernel(
    const float* __restrict__ feat, const float* __restrict__ knn_xyz,
    const float* __restrict__ knn_feat, const void* __restrict__ knn_mask,
    float* __restrict__ out_xyz, float* __restrict__ out_att, float* __restrict__ out_ml)
{
    __shared__ __align__(16) float kfS[2][KNB * CDIM];   // 2 x 16 KB
    __shared__ __align__(16) float featS[2 * CDIM];      // rows n0, n0+1
    __shared__ __align__(16) float pqS[2][2][CDIM];      // [row][d-half][chan]
    __shared__ __align__(16) float pfS[2][2][CDIM];
    __shared__ float xyzS[2][KNB * 3];
    __shared__ float madjS[2][KNB];
    __shared__ float scS[2][KNB], mlS[2][KNB], attnS[2][KNB];
    __shared__ float redS[2][4];

    int tid  = threadIdx.x;
    int h    = tid >> 7;     // half (= row within pair, = d-half for projection)
    int t    = tid & 127;
    int lane = t & 31;
    int w4   = t >> 5;       // warp within half (0..3)
    int n0   = blockIdx.x * 2;
    int n    = n0 + h;

    // G0: featS (both rows, contiguous 256 floats)
    if (tid < 64)
        cp_async16((float4*)featS + tid,
                   (const float4*)(feat + (size_t)n0 * CDIM) + tid);
    cp_async_commit();

    // G1: kf tile for this half's row
    {
        float4*       dst = reinterpret_cast<float4*>(kfS[h]);
        const float4* src = reinterpret_cast<const float4*>(knn_feat + (size_t)n * (KNB * CDIM));
#pragma unroll
        for (int i = 0; i < 8; i++)
            cp_async16(dst + i * 128 + t, src + i * 128 + t);
        cp_async_commit();
    }

    // overlapped small loads
    if (t < KNB * 3) xyzS[h][t] = knn_xyz[(size_t)n * (KNB * 3) + t];
    if (t < KNB) {
        bool mv;
        if (g_mask_narrow)
            mv = ((const unsigned char*)knn_mask)[(size_t)n * KNB + t] != 0;
        else
            mv = ((const unsigned int*)knn_mask)[(size_t)n * KNB + t] != 0u;
        madjS[h][t] = mv ? 0.f : -1e12f;
    }

    cp_async_wait<1>();      // featS landed (kf still streaming)
    __syncthreads();

    // ---- projection: thread (h, t) accumulates channel t over d in
    //      [64h, 64h+64) for BOTH rows, both matrices. Overlaps kf DRAM. ----
    {
        int d0 = h * 64;
        const float* Mp = g_M  + (size_t)d0 * CDIM + t;
        const float* Wp = g_Ws + (size_t)d0 * CDIM + t;
        const float* f0 = featS + d0;
        const float* f1 = featS + CDIM + d0;
        float pq0 = 0.f, pq1 = 0.f, pf0 = 0.f, pf1 = 0.f;
#pragma unroll 8
        for (int d = 0; d < 64; d++) {
            float m  = __ldg(Mp + d * CDIM);
            float w  = __ldg(Wp + d * CDIM);
            float a0 = f0[d];
            float a1 = f1[d];
            pq0 += a0 * m;  pq1 += a1 * m;
            pf0 += a0 * w;  pf1 += a1 * w;
        }
        pqS[0][h][t] = pq0;  pqS[1][h][t] = pq1;
        pfS[0][h][t] = pf0;  pfS[1][h][t] = pf1;
    }

    cp_async_wait<0>();      // kf landed
    __syncthreads();         // partials + kf visible

    // combine projection halves for this row's quad (registers)
    float4 qv, fv;
    {
        float4 qa = *(const float4*)&pqS[h][0][lane * 4];
        float4 qb = *(const float4*)&pqS[h][1][lane * 4];
        float4 fa = *(const float4*)&pfS[h][0][lane * 4];
        float4 fb = *(const float4*)&pfS[h][1][lane * 4];
        qv = make_float4(qa.x + qb.x, qa.y + qb.y, qa.z + qb.z, qa.w + qb.w);
        fv = make_float4(fa.x + fb.x, fa.y + fb.y, fa.z + fb.z, fa.w + fb.w);
    }

    // dots: warp w4 handles neighbors 8*w4 .. 8*w4+7 of row n
    int j0 = w4 * 8;
    float s[8], ml[8];
#pragma unroll
    for (int jj = 0; jj < 8; jj++) {
        float4 k4 = reinterpret_cast<const float4*>(kfS[h] + (j0 + jj) * CDIM)[lane];
        s [jj] = k4.x * qv.x + k4.y * qv.y + k4.z * qv.z + k4.w * qv.w;
        ml[jj] = k4.x * fv.x + k4.y * fv.y + k4.z * fv.z + k4.w * fv.w;
    }
#pragma unroll
    for (int o = 16; o; o >>= 1) {
#pragma unroll
        for (int jj = 0; jj < 8; jj++) {
            s [jj] += __shfl_xor_sync(0xffffffffu, s [jj], o);
            ml[jj] += __shfl_xor_sync(0xffffffffu, ml[jj], o);
        }
    }
#pragma unroll
    for (int jj = 0; jj < 8; jj++) {
        if (lane == jj) {
            scS[h][j0 + jj] = s[jj] + madjS[h][j0 + jj];
            mlS[h][j0 + jj] = ml[jj];
        }
    }
    __syncthreads();

    // topk rank + colmask + optimistic softmax (first warp of each half)
    if (t < KNB) {
        float sj = scS[h][t];
        int rank = 0;
#pragma unroll
        for (int i = 0; i < KNB; i++) {
            float si = scS[h][i];
            rank += (si > sj) || (si == sj && i < t);   // lax.top_k stable tie rule
        }
        if (rank < TOPK) {
            if (__ldcg(&g_colmask[t]) == 0) atomicOr(&g_colmask[t], 1);
        }
        g_scores[(size_t)n * KNB + t] = sj;
        out_ml[(size_t)n * KNB + t]   = mlS[h][t];

        float m = sj;
#pragma unroll
        for (int o = 16; o; o >>= 1) m = fmaxf(m, __shfl_xor_sync(0xffffffffu, m, o));
        float e = __expf(sj - m);
        float ssum = e;
#pragma unroll
        for (int o = 16; o; o >>= 1) ssum += __shfl_xor_sync(0xffffffffu, ssum, o);
        attnS[h][t] = e / ssum;
    }
    __syncthreads();

    // weighted sums + outputs (optimistic: all columns covered)
    float a0 = 0.f, a1 = 0.f, a2 = 0.f, a3 = 0.f;
#pragma unroll
    for (int j = 0; j < KNB; j += 4) {
        a0 += attnS[h][j    ] * kfS[h][(j    ) * CDIM + t];
        a1 += attnS[h][j + 1] * kfS[h][(j + 1) * CDIM + t];
        a2 += attnS[h][j + 2] * kfS[h][(j + 2) * CDIM + t];
        a3 += attnS[h][j + 3] * kfS[h][(j + 3) * CDIM + t];
    }
    float acc = (a0 + a1) + (a2 + a3);

    size_t ob = (size_t)n * 257;
    out_att[ob + t]       = featS[h * CDIM + t];  // attentive_feats[:, 0:128]
    out_att[ob + 128 + t] = acc;                  // attentive_feats[:, 128:256]

    float fw_t = pfS[h][0][t] + pfS[h][1][t];
    float p = fw_t * acc;
#pragma unroll
    for (int o = 16; o; o >>= 1) p += __shfl_xor_sync(0xffffffffu, p, o);
    if (lane == 0) redS[h][w4] = p;
    __syncthreads();
    if (t == 0)
        out_att[ob + 256] = redS[h][0] + redS[h][1] + redS[h][2] + redS[h][3];  // logit

    if (t < 3) {
        float x = 0.f;
#pragma unroll
        for (int j = 0; j < KNB; j++) x += attnS[h][j] * xyzS[h][j * 3 + t];
        out_xyz[(size_t)n * 3 + t] = x;
    }
}

// ---------------- K2: check whether any column never made top-k ----------------
__global__ void check_kernel() {
    int t = threadIdx.x;
    int miss = (t < KNB && g_colmask[t] == 0) ? 1 : 0;
#pragma unroll
    for (int o = 16; o; o >>= 1) miss |= __shfl_xor_sync(0xffffffffu, miss, o);
    if (t == 0) g_needfix = miss;
}

// ---------------- K3: fixup (rare path; recomputes fW from g_Ws) ----------------
__global__ void __launch_bounds__(128) fixup_kernel(
    const float* __restrict__ feat, const float* __restrict__ knn_feat,
    const float* __restrict__ knn_xyz,
    float* __restrict__ out_xyz, float* __restrict__ out_att)
{
    if (g_needfix == 0) return;   // common case

    __shared__ float attnS[KNB];
    __shared__ float redS[4];
    __shared__ int   colS[KNB];
    int tid = threadIdx.x, lane = tid & 31, warp = tid >> 5;
    if (tid < KNB) colS[tid] = g_colmask[tid];
    __syncthreads();

    for (int n = blockIdx.x; n < NROWS; n += gridDim.x) {
        if (tid < KNB) {
            float s  = g_scores[(size_t)n * KNB + tid];
            int inc  = colS[tid];
            float se = inc ? s : -3.0e38f;
            float m = se;
#pragma unroll
            for (int o = 16; o; o >>= 1) m = fmaxf(m, __shfl_xor_sync(0xffffffffu, m, o));
            float e = inc ? __expf(se - m) : 0.f;
            float ssum = e;
#pragma unroll
            for (int o = 16; o; o >>= 1) ssum += __shfl_xor_sync(0xffffffffu, ssum, o);
            attnS[tid] = e / ssum;
        }
        __syncthreads();

        float acc = 0.f;
#pragma unroll
        for (int j = 0; j < KNB; j++)
            acc += attnS[j] * knn_feat[(size_t)n * (KNB * CDIM) + j * CDIM + tid];

        size_t ob = (size_t)n * 257;
        out_att[ob + 128 + tid] = acc;

        // recompute fW row (no persistent fW scratch)
        float fwv = 0.f;
#pragma unroll 8
        for (int d = 0; d < CDIM; d++)
            fwv += __ldg(&feat[(size_t)n * CDIM + d]) * g_Ws[d * CDIM + tid];

        float p = fwv * acc;
#pragma unroll
        for (int o = 16; o; o >>= 1) p += __shfl_xor_sync(0xffffffffu, p, o);
        if (lane == 0) redS[warp] = p;
        __syncthreads();
        if (tid == 0) out_att[ob + 256] = redS[0] + redS[1] + redS[2] + redS[3];

        if (tid < 3) {
            float x = 0.f;
#pragma unroll
            for (int j = 0; j < KNB; j++)
                x += attnS[j] * knn_xyz[(size_t)n * (KNB * 3) + j * 3 + tid];
            out_xyz[(size_t)n * 3 + tid] = x;
        }
        __syncthreads();
    }
}

// ---------------- launch ----------------
extern "C" void kernel_launch(void* const* d_in, const int* in_sizes, int n_in,
                              void* d_out, int out_size) {
    const float* feat     = (const float*)d_in[0];          // [N,128]
    const float* knn_xyz  = (const float*)d_in[1];          // [N,32,3]
    const float* knn_feat = (const float*)d_in[2];          // [N,32,128]
    const void*  knn_mask = d_in[3];                        // [N,32] bool (width sniffed)
    const float* Wq       = (const float*)d_in[4];          // [128,128]
    const float* Wk       = (const float*)d_in[5];          // [128,128]
    const float* W        = (const float*)d_in[6];          // [128,128]

    float* out     = (float*)d_out;
    float* out_xyz = out;                                   // [N,3]
    float* out_att = out + (size_t)NROWS * 3;               // [N,257]
    float* out_ml  = out + (size_t)NROWS * 3 + (size_t)NROWS * 257;  // [N,32]

    prep_kernel<<<CDIM, CDIM>>>(Wq, Wk, W);
    sniff_kernel<<<512, 256>>>((const unsigned int*)knn_mask);

    main_kernel<<<NROWS / 2, 256>>>(feat, knn_xyz, knn_feat, knn_mask,
                                    out_xyz, out_att, out_ml);

    check_kernel<<<1, 32>>>();
    fixup_kernel<<<2048, CDIM>>>(feat, knn_feat, knn_xyz, out_xyz, out_att);
}

// round 9
// speedup vs baseline: 1.0595x; 1.0595x over previous
#include <cuda_runtime.h>
#include <cuda_bf16.h>
#include <cstdint>

#define NROWS 50000
#define KNB   32
#define CDIM  128
#define TOPK  16
#define RL    8            // rows per half per block

// ring slot layout (floats)
#define SLOTF     4608
#define OFF_KF    0        // 32*128 kf tile
#define OFF_QM    4096     // 128 qM row
#define OFF_FW    4224     // 128 fW row
#define OFF_XYZ   4352     // 96  xyz row
#define OFF_MASK  4448     // raw mask bytes (up to 128B)
#define MAIN_SMEM (2 * 2 * SLOTF * 4)   // 73728 B dynamic

// ---------------- scratch (device globals; no allocation) ----------------
__device__ __align__(16) float g_M [CDIM * CDIM];     // Wq^T @ Wk
__device__ __align__(16) float g_Ws[CDIM * CDIM];     // triu(W) + triu(W)^T
__device__ __align__(16) float g_qM[(size_t)NROWS * CDIM];  // feat @ M
__device__ __align__(16) float g_fW[(size_t)NROWS * CDIM];  // feat @ Ws
__device__ __align__(16) float g_scores[(size_t)NROWS * KNB];
__device__ int g_colmask[KNB];
__device__ int g_needfix;
__device__ int g_mask_narrow;   // 1 -> mask elements are 1 byte; 0 -> 4 bytes

// ---------------- cp.async helpers ----------------
__device__ __forceinline__ void cp_async16(void* smem_dst, const void* gptr) {
    uint32_t s = (uint32_t)__cvta_generic_to_shared(smem_dst);
    asm volatile("cp.async.cg.shared.global [%0], [%1], 16;\n" :: "r"(s), "l"(gptr));
}
__device__ __forceinline__ void cp_async_commit() {
    asm volatile("cp.async.commit_group;\n" ::: "memory");
}
template <int N> __device__ __forceinline__ void cp_async_wait() {
    asm volatile("cp.async.wait_group %0;\n" :: "n"(N) : "memory");
}

// ---------------- K0: prep M, Ws, reset flags ----------------
__global__ void prep_kernel(const float* __restrict__ Wq,
                            const float* __restrict__ Wk,
                            const float* __restrict__ W) {
    int c = blockIdx.x;    // 0..127
    int e = threadIdx.x;   // 0..127
    float acc = 0.f;
#pragma unroll 8
    for (int d = 0; d < CDIM; d++)
        acc += Wq[d * CDIM + c] * Wk[d * CDIM + e];
    g_M[c * CDIM + e] = acc;

    float w = (c <= e) ? W[c * CDIM + e] : W[e * CDIM + c];
    g_Ws[c * CDIM + e] = (c == e) ? 2.f * w : w;

    if (c == 0 && e < KNB) g_colmask[e] = 0;
    if (c == 0 && e == KNB) g_needfix = 0;
    if (c == 0 && e == KNB + 1) g_mask_narrow = 0;
}

// ---------------- K0b: sniff knn_mask element width ----------------
__global__ void sniff_kernel(const unsigned int* __restrict__ w) {
    const int nwords = NROWS * KNB / 4;
    int bad = 0;
    for (int i = blockIdx.x * blockDim.x + threadIdx.x; i < nwords;
         i += gridDim.x * blockDim.x) {
        unsigned int v = w[i];
        if (v != 0u && v != 1u && v != 0x3F800000u) bad = 1;
    }
    if (bad) g_mask_narrow = 1;
}

// ---------------- K1: SGEMM v3 (unchanged from R7) ----------------
__global__ void __launch_bounds__(256, 2) gemm_kernel(const float* __restrict__ A) {
    __shared__ __align__(16) float As[64 * 128];   // 32 KB

    int tid  = threadIdx.x;
    int row0 = blockIdx.x * 64;

    for (int i = tid; i < 64 * 32; i += 256) {     // float4 units
        int r = i >> 5;
        float4 v = make_float4(0.f, 0.f, 0.f, 0.f);
        if (row0 + r < NROWS)
            v = reinterpret_cast<const float4*>(A)[(size_t)(row0 + r) * 32 + (i & 31)];
        reinterpret_cast<float4*>(As)[i] = v;
    }
    __syncthreads();

    int cq = tid & 15;
    int rg = tid >> 4;
    float accM[4][8], accW[4][8];
#pragma unroll
    for (int i = 0; i < 4; i++)
#pragma unroll
        for (int j = 0; j < 8; j++) { accM[i][j] = 0.f; accW[i][j] = 0.f; }

    const float* Arow = As + rg * 4 * 128;
#pragma unroll 4
    for (int k = 0; k < 128; k++) {
        float a[4];
#pragma unroll
        for (int i = 0; i < 4; i++) a[i] = Arow[i * 128 + k];
        float4 m0 = __ldg((const float4*)(g_M  + k * 128 + cq * 8));
        float4 m1 = __ldg((const float4*)(g_M  + k * 128 + cq * 8 + 4));
        float4 w0 = __ldg((const float4*)(g_Ws + k * 128 + cq * 8));
        float4 w1 = __ldg((const float4*)(g_Ws + k * 128 + cq * 8 + 4));
        float bm[8] = {m0.x, m0.y, m0.z, m0.w, m1.x, m1.y, m1.z, m1.w};
        float bw[8] = {w0.x, w0.y, w0.z, w0.w, w1.x, w1.y, w1.z, w1.w};
#pragma unroll
        for (int i = 0; i < 4; i++)
#pragma unroll
            for (int j = 0; j < 8; j++) {
                accM[i][j] += a[i] * bm[j];
                accW[i][j] += a[i] * bw[j];
            }
    }

#pragma unroll
    for (int i = 0; i < 4; i++) {
        int r = row0 + rg * 4 + i;
        if (r < NROWS) {
            float4* pq = reinterpret_cast<float4*>(g_qM + (size_t)r * 128 + cq * 8);
            float4* pf = reinterpret_cast<float4*>(g_fW + (size_t)r * 128 + cq * 8);
            pq[0] = make_float4(accM[i][0], accM[i][1], accM[i][2], accM[i][3]);
            pq[1] = make_float4(accM[i][4], accM[i][5], accM[i][6], accM[i][7]);
            pf[0] = make_float4(accW[i][0], accW[i][1], accW[i][2], accW[i][3]);
            pf[1] = make_float4(accW[i][4], accW[i][5], accW[i][6], accW[i][7]);
        }
    }
}

// ---------------- K2: pipelined streaming kernel ----------------
// 2 independent 128-thread halves; each loops over RL=8 rows with a
// depth-2 cp.async ring (row r+1 streams while row r computes).
__global__ void __launch_bounds__(256, 3) main_kernel(
    const float* __restrict__ feat, const float* __restrict__ knn_xyz,
    const float* __restrict__ knn_feat, const void* __restrict__ knn_mask,
    float* __restrict__ out_xyz, float* __restrict__ out_att, float* __restrict__ out_ml)
{
    extern __shared__ float dyn[];
    __shared__ float scS[2][KNB], mlS[2][KNB], attnS[2][KNB], redS[2][4];

    int tid  = threadIdx.x;
    int h    = tid >> 7;
    int t    = tid & 127;
    int lane = t & 31;
    int w4   = t >> 5;
    int narrow = g_mask_narrow;
    int nbase  = blockIdx.x * (2 * RL) + h * RL;

    float* ring = dyn + h * 2 * SLOTF;

    // issue all cp.asyncs for row (nbase + r) into slot r&1
    auto issue_row = [&](int r) {
        float* S = ring + (r & 1) * SLOTF;
        size_t n = (size_t)(nbase + r);
        const float4* kf = (const float4*)(knn_feat + n * (KNB * CDIM));
        float4* kd = (float4*)(S + OFF_KF);
#pragma unroll
        for (int i = 0; i < 8; i++)
            cp_async16(kd + i * 128 + t, kf + i * 128 + t);
        if (t < 32) {
            cp_async16((float4*)(S + OFF_QM) + t, (const float4*)(g_qM + n * CDIM) + t);
        } else if (t < 64) {
            cp_async16((float4*)(S + OFF_FW) + (t - 32),
                       (const float4*)(g_fW + n * CDIM) + (t - 32));
        } else if (t < 88) {
            cp_async16((float4*)(S + OFF_XYZ) + (t - 64),
                       (const float4*)(knn_xyz + n * 96) + (t - 64));
        } else if (narrow) {
            if (t < 90)
                cp_async16((float4*)(S + OFF_MASK) + (t - 88),
                           (const float4*)((const char*)knn_mask + n * 32) + (t - 88));
        } else {
            if (t < 96)
                cp_async16((float4*)(S + OFF_MASK) + (t - 88),
                           (const float4*)((const char*)knn_mask + n * 128) + (t - 88));
        }
    };

    issue_row(0);
    cp_async_commit();
    float fcN = __ldg(&feat[(size_t)nbase * CDIM + t]);   // feat row prefetch (reg)

    for (int r = 0; r < RL; r++) {
        int n = nbase + r;
        float* S = ring + (r & 1) * SLOTF;

        if (r + 1 < RL) { issue_row(r + 1); cp_async_commit(); cp_async_wait<1>(); }
        else            { cp_async_wait<0>(); }
        __syncthreads();                         // slot r visible to all

        float fc = fcN;
        if (r + 1 < RL) fcN = __ldg(&feat[(size_t)(n + 1) * CDIM + t]);

        // dots: warp w4 -> neighbors 8*w4 .. 8*w4+7
        float4 qv = reinterpret_cast<const float4*>(S + OFF_QM)[lane];
        float4 fv = reinterpret_cast<const float4*>(S + OFF_FW)[lane];
        int j0 = w4 * 8;
        float s[8], ml[8];
#pragma unroll
        for (int jj = 0; jj < 8; jj++) {
            float4 k4 = reinterpret_cast<const float4*>(S + OFF_KF + (j0 + jj) * CDIM)[lane];
            s [jj] = k4.x * qv.x + k4.y * qv.y + k4.z * qv.z + k4.w * qv.w;
            ml[jj] = k4.x * fv.x + k4.y * fv.y + k4.z * fv.z + k4.w * fv.w;
        }
#pragma unroll
        for (int o = 16; o; o >>= 1) {
#pragma unroll
            for (int jj = 0; jj < 8; jj++) {
                s [jj] += __shfl_xor_sync(0xffffffffu, s [jj], o);
                ml[jj] += __shfl_xor_sync(0xffffffffu, ml[jj], o);
            }
        }
#pragma unroll
        for (int jj = 0; jj < 8; jj++) {
            if (lane == jj) {
                int j = j0 + jj;
                float adj;
                if (narrow)
                    adj = ((const unsigned char*)(S + OFF_MASK))[j] ? 0.f : -1e12f;
                else
                    adj = ((const unsigned int*)(S + OFF_MASK))[j] ? 0.f : -1e12f;
                scS[h][j] = s[jj] + adj;
                mlS[h][j] = ml[jj];
            }
        }
        __syncthreads();

        // topk rank + colmask + optimistic softmax (first warp of each half)
        if (t < KNB) {
            float sj = scS[h][t];
            int rank = 0;
#pragma unroll
            for (int i = 0; i < KNB; i++) {
                float si = scS[h][i];
                rank += (si > sj) || (si == sj && i < t);   // lax.top_k stable tie rule
            }
            if (rank < TOPK) {
                if (__ldcg(&g_colmask[t]) == 0) atomicOr(&g_colmask[t], 1);
            }
            g_scores[(size_t)n * KNB + t] = sj;
            out_ml[(size_t)n * KNB + t]   = mlS[h][t];

            float m = sj;
#pragma unroll
            for (int o = 16; o; o >>= 1) m = fmaxf(m, __shfl_xor_sync(0xffffffffu, m, o));
            float e = __expf(sj - m);
            float ssum = e;
#pragma unroll
            for (int o = 16; o; o >>= 1) ssum += __shfl_xor_sync(0xffffffffu, ssum, o);
            attnS[h][t] = e / ssum;
        }
        __syncthreads();

        // weighted sums + outputs (optimistic: all columns covered)
        const float* kfp = S + OFF_KF;
        float a0 = 0.f, a1 = 0.f, a2 = 0.f, a3 = 0.f;
#pragma unroll
        for (int j = 0; j < KNB; j += 4) {
            a0 += attnS[h][j    ] * kfp[(j    ) * CDIM + t];
            a1 += attnS[h][j + 1] * kfp[(j + 1) * CDIM + t];
            a2 += attnS[h][j + 2] * kfp[(j + 2) * CDIM + t];
            a3 += attnS[h][j + 3] * kfp[(j + 3) * CDIM + t];
        }
        float acc = (a0 + a1) + (a2 + a3);

        size_t ob = (size_t)n * 257;
        out_att[ob + t]       = fc;     // attentive_feats[:, 0:128]
        out_att[ob + 128 + t] = acc;    // attentive_feats[:, 128:256]

        float p = (S + OFF_FW)[t] * acc;
#pragma unroll
        for (int o = 16; o; o >>= 1) p += __shfl_xor_sync(0xffffffffu, p, o);
        if (lane == 0) redS[h][w4] = p;
        __syncthreads();
        if (t == 0)
            out_att[ob + 256] = redS[h][0] + redS[h][1] + redS[h][2] + redS[h][3];
        if (t < 3) {
            float x = 0.f;
#pragma unroll
            for (int j = 0; j < KNB; j++) x += attnS[h][j] * (S + OFF_XYZ)[j * 3 + t];
            out_xyz[(size_t)n * 3 + t] = x;
        }
        __syncthreads();   // all reads of slot r done before it is overwritten
    }
}

// ---------------- K3: check whether any column never made top-k ----------------
__global__ void check_kernel() {
    int t = threadIdx.x;
    int miss = (t < KNB && g_colmask[t] == 0) ? 1 : 0;
#pragma unroll
    for (int o = 16; o; o >>= 1) miss |= __shfl_xor_sync(0xffffffffu, miss, o);
    if (t == 0) g_needfix = miss;
}

// ---------------- K4: fixup (early-exits when colmask is all-covered) ----------------
__global__ void __launch_bounds__(128) fixup_kernel(
    const float* __restrict__ knn_feat, const float* __restrict__ knn_xyz,
    float* __restrict__ out_xyz, float* __restrict__ out_att)
{
    if (g_needfix == 0) return;   // common case

    __shared__ float attnS[KNB];
    __shared__ float redS[4];
    __shared__ int   colS[KNB];
    int tid = threadIdx.x, lane = tid & 31, warp = tid >> 5;
    if (tid < KNB) colS[tid] = g_colmask[tid];
    __syncthreads();

    for (int n = blockIdx.x; n < NROWS; n += gridDim.x) {
        if (tid < KNB) {
            float s  = g_scores[(size_t)n * KNB + tid];
            int inc  = colS[tid];
            float se = inc ? s : -3.0e38f;
            float m = se;
#pragma unroll
            for (int o = 16; o; o >>= 1) m = fmaxf(m, __shfl_xor_sync(0xffffffffu, m, o));
            float e = inc ? __expf(se - m) : 0.f;
            float ssum = e;
#pragma unroll
            for (int o = 16; o; o >>= 1) ssum += __shfl_xor_sync(0xffffffffu, ssum, o);
            attnS[tid] = e / ssum;
        }
        __syncthreads();

        float acc = 0.f;
#pragma unroll
        for (int j = 0; j < KNB; j++)
            acc += attnS[j] * knn_feat[(size_t)n * (KNB * CDIM) + j * CDIM + tid];

        size_t ob = (size_t)n * 257;
        out_att[ob + 128 + tid] = acc;

        float p = g_fW[(size_t)n * CDIM + tid] * acc;
#pragma unroll
        for (int o = 16; o; o >>= 1) p += __shfl_xor_sync(0xffffffffu, p, o);
        if (lane == 0) redS[warp] = p;
        __syncthreads();
        if (tid == 0) out_att[ob + 256] = redS[0] + redS[1] + redS[2] + redS[3];

        if (tid < 3) {
            float x = 0.f;
#pragma unroll
            for (int j = 0; j < KNB; j++)
                x += attnS[j] * knn_xyz[(size_t)n * (KNB * 3) + j * 3 + tid];
            out_xyz[(size_t)n * 3 + tid] = x;
        }
        __syncthreads();
    }
}

// ---------------- launch ----------------
extern "C" void kernel_launch(void* const* d_in, const int* in_sizes, int n_in,
                              void* d_out, int out_size) {
    const float* feat     = (const float*)d_in[0];          // [N,128]
    const float* knn_xyz  = (const float*)d_in[1];          // [N,32,3]
    const float* knn_feat = (const float*)d_in[2];          // [N,32,128]
    const void*  knn_mask = d_in[3];                        // [N,32] bool (width sniffed)
    const float* Wq       = (const float*)d_in[4];          // [128,128]
    const float* Wk       = (const float*)d_in[5];          // [128,128]
    const float* W        = (const float*)d_in[6];          // [128,128]

    float* out     = (float*)d_out;
    float* out_xyz = out;                                   // [N,3]
    float* out_att = out + (size_t)NROWS * 3;               // [N,257]
    float* out_ml  = out + (size_t)NROWS * 3 + (size_t)NROWS * 257;  // [N,32]

    prep_kernel<<<CDIM, CDIM>>>(Wq, Wk, W);
    sniff_kernel<<<512, 256>>>((const unsigned int*)knn_mask);

    gemm_kernel<<<(NROWS + 63) / 64, 256>>>(feat);

    cudaFuncSetAttribute(main_kernel, cudaFuncAttributeMaxDynamicSharedMemorySize,
                         MAIN_SMEM);
    main_kernel<<<NROWS / (2 * RL), 256, MAIN_SMEM>>>(
        feat, knn_xyz, knn_feat, knn_mask, out_xyz, out_att, out_ml);

    check_kernel<<<1, 32>>>();
    fixup_kernel<<<2048, CDIM>>>(knn_feat, knn_xyz, out_xyz, out_att);
}

// round 10
// speedup vs baseline: 1.1001x; 1.0383x over previous
#include <cuda_runtime.h>
#include <cuda_bf16.h>
#include <cstdint>

#define NROWS 50000
#define KNB   32
#define CDIM  128
#define TOPK  16

// ---------------- scratch (device globals; no allocation) ----------------
__device__ __align__(16) float g_M [CDIM * CDIM];     // Wq^T @ Wk
__device__ __align__(16) float g_Ws[CDIM * CDIM];     // triu(W) + triu(W)^T
__device__ __align__(16) float g_qM[(size_t)NROWS * CDIM];  // feat @ M
__device__ __align__(16) float g_fW[(size_t)NROWS * CDIM];  // feat @ Ws
__device__ __align__(16) float g_scores[(size_t)NROWS * KNB];
__device__ int g_colmask[KNB];
__device__ int g_needfix;
__device__ int g_mask_narrow;   // 1 -> mask elements are 1 byte; 0 -> 4 bytes

// per-half named barrier (ids 1,2), 128 threads each
__device__ __forceinline__ void half_sync(int h) {
    asm volatile("bar.sync %0, 128;" :: "r"(h + 1) : "memory");
}

// ---------------- K0: prep M, Ws, reset flags ----------------
__global__ void prep_kernel(const float* __restrict__ Wq,
                            const float* __restrict__ Wk,
                            const float* __restrict__ W) {
    int c = blockIdx.x;    // 0..127
    int e = threadIdx.x;   // 0..127
    float acc = 0.f;
#pragma unroll 8
    for (int d = 0; d < CDIM; d++)
        acc += Wq[d * CDIM + c] * Wk[d * CDIM + e];
    g_M[c * CDIM + e] = acc;

    float w = (c <= e) ? W[c * CDIM + e] : W[e * CDIM + c];
    g_Ws[c * CDIM + e] = (c == e) ? 2.f * w : w;

    if (c == 0 && e < KNB) g_colmask[e] = 0;
    if (c == 0 && e == KNB) g_needfix = 0;
    if (c == 0 && e == KNB + 1) g_mask_narrow = 0;
}

// ---------------- K0b: sniff knn_mask element width ----------------
__global__ void sniff_kernel(const unsigned int* __restrict__ w) {
    const int nwords = NROWS * KNB / 4;
    int bad = 0;
    for (int i = blockIdx.x * blockDim.x + threadIdx.x; i < nwords;
         i += gridDim.x * blockDim.x) {
        unsigned int v = w[i];
        if (v != 0u && v != 1u && v != 0x3F800000u) bad = 1;
    }
    if (bad) g_mask_narrow = 1;
}

// ---------------- K1: SGEMM v4 — matrix-split 512-thread blocks ----------------
// 64-row A tile in smem (32KB), shared by both halves. Threads 0-255: feat@M,
// threads 256-511: feat@Ws. Microtile 4x8x1 -> ~56 regs -> 2 CTA/SM = 32 warps.
__global__ void __launch_bounds__(512, 2) gemm_kernel(const float* __restrict__ A) {
    __shared__ __align__(16) float As[64 * 128];   // 32 KB

    int tid  = threadIdx.x;
    int half = tid >> 8;          // 0 -> M, 1 -> Ws
    int t    = tid & 255;
    int row0 = blockIdx.x * 64;

    for (int i = tid; i < 64 * 32; i += 512) {     // float4 units
        int r = i >> 5;
        float4 v = make_float4(0.f, 0.f, 0.f, 0.f);
        if (row0 + r < NROWS)
            v = reinterpret_cast<const float4*>(A)[(size_t)(row0 + r) * 32 + (i & 31)];
        reinterpret_cast<float4*>(As)[i] = v;
    }
    __syncthreads();

    const float* __restrict__ B   = half ? g_Ws : g_M;
    float*       __restrict__ Out = half ? g_fW : g_qM;

    int cq = t & 15;   // cols cq*8 .. cq*8+7
    int rg = t >> 4;   // rows rg*4 .. rg*4+3
    float acc[4][8];
#pragma unroll
    for (int i = 0; i < 4; i++)
#pragma unroll
        for (int j = 0; j < 8; j++) acc[i][j] = 0.f;

    const float* Arow = As + rg * 4 * 128;
#pragma unroll 8
    for (int k = 0; k < 128; k++) {
        float a[4];
#pragma unroll
        for (int i = 0; i < 4; i++) a[i] = Arow[i * 128 + k];
        float4 b0 = __ldg((const float4*)(B + k * 128 + cq * 8));
        float4 b1 = __ldg((const float4*)(B + k * 128 + cq * 8 + 4));
        float b[8] = {b0.x, b0.y, b0.z, b0.w, b1.x, b1.y, b1.z, b1.w};
#pragma unroll
        for (int i = 0; i < 4; i++)
#pragma unroll
            for (int j = 0; j < 8; j++) acc[i][j] += a[i] * b[j];
    }

#pragma unroll
    for (int i = 0; i < 4; i++) {
        int r = row0 + rg * 4 + i;
        if (r < NROWS) {
            float4* p = reinterpret_cast<float4*>(Out + (size_t)r * 128 + cq * 8);
            p[0] = make_float4(acc[i][0], acc[i][1], acc[i][2], acc[i][3]);
            p[1] = make_float4(acc[i][4], acc[i][5], acc[i][6], acc[i][7]);
        }
    }
}

// ---------------- K2: LDG-direct streaming kernel ----------------
// 2 rows per 256-thread block (independent 128-thread halves, named barriers).
// kf read twice via L1 (cold in phase 1, hits in phase 3); no cp.async/smem tile.
__global__ void __launch_bounds__(256, 5) main_kernel(
    const float* __restrict__ feat, const float* __restrict__ knn_xyz,
    const float* __restrict__ knn_feat, const void* __restrict__ knn_mask,
    float* __restrict__ out_xyz, float* __restrict__ out_att, float* __restrict__ out_ml)
{
    __shared__ float xyzS[2][KNB * 3];
    __shared__ float madjS[2][KNB];
    __shared__ float scS[2][KNB], mlS[2][KNB], attnS[2][KNB];
    __shared__ __align__(16) float pwS[2][4][CDIM];   // per-warp wsum partials
    __shared__ float redS[2][4];

    int tid  = threadIdx.x;
    int h    = tid >> 7;
    int t    = tid & 127;
    int lane = t & 31;
    int w4   = t >> 5;
    int n    = blockIdx.x * 2 + h;

    // small inputs (warp0: mask; warps 0-2: xyz) — consumed only after barriers
    if (t < KNB) {
        bool mv;
        if (g_mask_narrow)
            mv = ((const unsigned char*)knn_mask)[(size_t)n * KNB + t] != 0;
        else
            mv = ((const unsigned int*)knn_mask)[(size_t)n * KNB + t] != 0u;
        madjS[h][t] = mv ? 0.f : -1e12f;
    }
    if (t < KNB * 3) xyzS[h][t] = __ldg(&knn_xyz[(size_t)n * (KNB * 3) + t]);

    // phase 1: dots straight from global (through L1)
    const float4* kf4 = reinterpret_cast<const float4*>(knn_feat + (size_t)n * (KNB * CDIM));
    float4 qv = __ldg(reinterpret_cast<const float4*>(g_qM + (size_t)n * CDIM) + lane);
    float4 fv = __ldg(reinterpret_cast<const float4*>(g_fW + (size_t)n * CDIM) + lane);

    int j0 = w4 * 8;
    float s[8], ml[8];
#pragma unroll
    for (int jj = 0; jj < 8; jj++) {
        float4 k4 = __ldg(kf4 + (j0 + jj) * 32 + lane);
        s [jj] = k4.x * qv.x + k4.y * qv.y + k4.z * qv.z + k4.w * qv.w;
        ml[jj] = k4.x * fv.x + k4.y * fv.y + k4.z * fv.z + k4.w * fv.w;
    }
#pragma unroll
    for (int o = 16; o; o >>= 1) {
#pragma unroll
        for (int jj = 0; jj < 8; jj++) {
            s [jj] += __shfl_xor_sync(0xffffffffu, s [jj], o);
            ml[jj] += __shfl_xor_sync(0xffffffffu, ml[jj], o);
        }
    }
#pragma unroll
    for (int jj = 0; jj < 8; jj++) {
        if (lane == jj) {
            scS[h][j0 + jj] = s[jj];      // raw scores; mask applied by warp 0
            mlS[h][j0 + jj] = ml[jj];
        }
    }
    half_sync(h);

    // phase 2 (warp 0 of half): mask + topk rank + colmask + softmax
    if (t < KNB) {
        float sj = scS[h][t] + madjS[h][t];
        int rank = 0;
#pragma unroll
        for (int i = 0; i < KNB; i++) {
            float si = scS[h][i] + madjS[h][i];
            rank += (si > sj) || (si == sj && i < t);   // lax.top_k stable tie rule
        }
        if (rank < TOPK) {
            if (__ldcg(&g_colmask[t]) == 0) atomicOr(&g_colmask[t], 1);
        }
        g_scores[(size_t)n * KNB + t] = sj;
        out_ml[(size_t)n * KNB + t]   = mlS[h][t];

        float m = sj;
#pragma unroll
        for (int o = 16; o; o >>= 1) m = fmaxf(m, __shfl_xor_sync(0xffffffffu, m, o));
        float e = __expf(sj - m);
        float ssum = e;
#pragma unroll
        for (int o = 16; o; o >>= 1) ssum += __shfl_xor_sync(0xffffffffu, ssum, o);
        attnS[h][t] = e / ssum;
    }
    half_sync(h);

    // phase 3: weighted sum — same addresses as phase 1 (L1 hits), per-warp
    // octet partials, then smem exchange.
    float4 acc4 = make_float4(0.f, 0.f, 0.f, 0.f);
#pragma unroll
    for (int jj = 0; jj < 8; jj++) {
        float  a  = attnS[h][j0 + jj];
        float4 k4 = __ldg(kf4 + (j0 + jj) * 32 + lane);
        acc4.x += a * k4.x; acc4.y += a * k4.y; acc4.z += a * k4.z; acc4.w += a * k4.w;
    }
    *reinterpret_cast<float4*>(&pwS[h][w4][lane * 4]) = acc4;
    half_sync(h);

    float c = pwS[h][0][t] + pwS[h][1][t] + pwS[h][2][t] + pwS[h][3][t];

    size_t ob = (size_t)n * 257;
    out_att[ob + t]       = __ldg(&feat[(size_t)n * CDIM + t]);  // feats[:,0:128]
    out_att[ob + 128 + t] = c;                                   // corres_feat

    float p = __ldg(&g_fW[(size_t)n * CDIM + t]) * c;
#pragma unroll
    for (int o = 16; o; o >>= 1) p += __shfl_xor_sync(0xffffffffu, p, o);
    if (lane == 0) redS[h][w4] = p;
    half_sync(h);
    if (t == 0)
        out_att[ob + 256] = redS[h][0] + redS[h][1] + redS[h][2] + redS[h][3];  // logit

    if (t < 3) {
        float x = 0.f;
#pragma unroll
        for (int j = 0; j < KNB; j++) x += attnS[h][j] * xyzS[h][j * 3 + t];
        out_xyz[(size_t)n * 3 + t] = x;
    }
}

// ---------------- K3: check whether any column never made top-k ----------------
__global__ void check_kernel() {
    int t = threadIdx.x;
    int miss = (t < KNB && g_colmask[t] == 0) ? 1 : 0;
#pragma unroll
    for (int o = 16; o; o >>= 1) miss |= __shfl_xor_sync(0xffffffffu, miss, o);
    if (t == 0) g_needfix = miss;
}

// ---------------- K4: fixup (early-exits when colmask is all-covered) ----------------
__global__ void __launch_bounds__(128) fixup_kernel(
    const float* __restrict__ knn_feat, const float* __restrict__ knn_xyz,
    float* __restrict__ out_xyz, float* __restrict__ out_att)
{
    if (g_needfix == 0) return;   // common case

    __shared__ float attnS[KNB];
    __shared__ float redS[4];
    __shared__ int   colS[KNB];
    int tid = threadIdx.x, lane = tid & 31, warp = tid >> 5;
    if (tid < KNB) colS[tid] = g_colmask[tid];
    __syncthreads();

    for (int n = blockIdx.x; n < NROWS; n += gridDim.x) {
        if (tid < KNB) {
            float s  = g_scores[(size_t)n * KNB + tid];
            int inc  = colS[tid];
            float se = inc ? s : -3.0e38f;
            float m = se;
#pragma unroll
            for (int o = 16; o; o >>= 1) m = fmaxf(m, __shfl_xor_sync(0xffffffffu, m, o));
            float e = inc ? __expf(se - m) : 0.f;
            float ssum = e;
#pragma unroll
            for (int o = 16; o; o >>= 1) ssum += __shfl_xor_sync(0xffffffffu, ssum, o);
            attnS[tid] = e / ssum;
        }
        __syncthreads();

        float acc = 0.f;
#pragma unroll
        for (int j = 0; j < KNB; j++)
            acc += attnS[j] * knn_feat[(size_t)n * (KNB * CDIM) + j * CDIM + tid];

        size_t ob = (size_t)n * 257;
        out_att[ob + 128 + tid] = acc;

        float p = g_fW[(size_t)n * CDIM + tid] * acc;
#pragma unroll
        for (int o = 16; o; o >>= 1) p += __shfl_xor_sync(0xffffffffu, p, o);
        if (lane == 0) redS[warp] = p;
        __syncthreads();
        if (tid == 0) out_att[ob + 256] = redS[0] + redS[1] + redS[2] + redS[3];

        if (tid < 3) {
            float x = 0.f;
#pragma unroll
            for (int j = 0; j < KNB; j++)
                x += attnS[j] * knn_xyz[(size_t)n * (KNB * 3) + j * 3 + tid];
            out_xyz[(size_t)n * 3 + tid] = x;
        }
        __syncthreads();
    }
}

// ---------------- launch ----------------
extern "C" void kernel_launch(void* const* d_in, const int* in_sizes, int n_in,
                              void* d_out, int out_size) {
    const float* feat     = (const float*)d_in[0];          // [N,128]
    const float* knn_xyz  = (const float*)d_in[1];          // [N,32,3]
    const float* knn_feat = (const float*)d_in[2];          // [N,32,128]
    const void*  knn_mask = d_in[3];                        // [N,32] bool (width sniffed)
    const float* Wq       = (const float*)d_in[4];          // [128,128]
    const float* Wk       = (const float*)d_in[5];          // [128,128]
    const float* W        = (const float*)d_in[6];          // [128,128]

    float* out     = (float*)d_out;
    float* out_xyz = out;                                   // [N,3]
    float* out_att = out + (size_t)NROWS * 3;               // [N,257]
    float* out_ml  = out + (size_t)NROWS * 3 + (size_t)NROWS * 257;  // [N,32]

    prep_kernel<<<CDIM, CDIM>>>(Wq, Wk, W);
    sniff_kernel<<<512, 256>>>((const unsigned int*)knn_mask);

    gemm_kernel<<<(NROWS + 63) / 64, 512>>>(feat);

    main_kernel<<<NROWS / 2, 256>>>(feat, knn_xyz, knn_feat, knn_mask,
                                    out_xyz, out_att, out_ml);

    check_kernel<<<1, 32>>>();
    fixup_kernel<<<2048, CDIM>>>(knn_feat, knn_xyz, out_xyz, out_att);
}

// round 11
// speedup vs baseline: 1.1115x; 1.0104x over previous
#include <cuda_runtime.h>
#include <cuda_bf16.h>
#include <cstdint>

#define NROWS 50000
#define KNB   32
#define CDIM  128
#define TOPK  16

// ---------------- scratch (device globals; no allocation) ----------------
__device__ __align__(16) float g_M [CDIM * CDIM];     // Wq^T @ Wk
__device__ __align__(16) float g_Ws[CDIM * CDIM];     // triu(W) + triu(W)^T
__device__ __align__(16) float g_qM[(size_t)NROWS * CDIM];  // feat @ M
__device__ __align__(16) float g_fW[(size_t)NROWS * CDIM];  // feat @ Ws
__device__ __align__(16) float g_scores[(size_t)NROWS * KNB];
__device__ int g_colmask[KNB];
__device__ int g_needfix;
__device__ int g_mask_narrow;   // 1 -> mask elements are 1 byte; 0 -> 4 bytes

// per-half named barrier (ids 1,2), 128 threads each
__device__ __forceinline__ void half_sync(int h) {
    asm volatile("bar.sync %0, 128;" :: "r"(h + 1) : "memory");
}

// ---------------- K0: prep M, Ws, reset flags ----------------
__global__ void prep_kernel(const float* __restrict__ Wq,
                            const float* __restrict__ Wk,
                            const float* __restrict__ W) {
    int c = blockIdx.x;    // 0..127
    int e = threadIdx.x;   // 0..127
    float acc = 0.f;
#pragma unroll 8
    for (int d = 0; d < CDIM; d++)
        acc += Wq[d * CDIM + c] * Wk[d * CDIM + e];
    g_M[c * CDIM + e] = acc;

    float w = (c <= e) ? W[c * CDIM + e] : W[e * CDIM + c];
    g_Ws[c * CDIM + e] = (c == e) ? 2.f * w : w;

    if (c == 0 && e < KNB) g_colmask[e] = 0;
    if (c == 0 && e == KNB) g_needfix = 0;
    if (c == 0 && e == KNB + 1) g_mask_narrow = 0;
}

// ---------------- K0b: sniff knn_mask element width ----------------
__global__ void sniff_kernel(const unsigned int* __restrict__ w) {
    const int nwords = NROWS * KNB / 4;
    int bad = 0;
    for (int i = blockIdx.x * blockDim.x + threadIdx.x; i < nwords;
         i += gridDim.x * blockDim.x) {
        unsigned int v = w[i];
        if (v != 0u && v != 1u && v != 0x3F800000u) bad = 1;
    }
    if (bad) g_mask_narrow = 1;
}

// ---------------- K1: SGEMM v4 — matrix-split 512-thread blocks ----------------
// 64-row A tile in smem (32KB), shared by both halves. Threads 0-255: feat@M,
// threads 256-511: feat@Ws. Microtile 4x8x1 -> ~56 regs -> 2 CTA/SM = 32 warps.
__global__ void __launch_bounds__(512, 2) gemm_kernel(const float* __restrict__ A) {
    __shared__ __align__(16) float As[64 * 128];   // 32 KB

    int tid  = threadIdx.x;
    int half = tid >> 8;          // 0 -> M, 1 -> Ws
    int t    = tid & 255;
    int row0 = blockIdx.x * 64;

    for (int i = tid; i < 64 * 32; i += 512) {     // float4 units
        int r = i >> 5;
        float4 v = make_float4(0.f, 0.f, 0.f, 0.f);
        if (row0 + r < NROWS)
            v = reinterpret_cast<const float4*>(A)[(size_t)(row0 + r) * 32 + (i & 31)];
        reinterpret_cast<float4*>(As)[i] = v;
    }
    __syncthreads();

    const float* __restrict__ B   = half ? g_Ws : g_M;
    float*       __restrict__ Out = half ? g_fW : g_qM;

    int cq = t & 15;   // cols cq*8 .. cq*8+7
    int rg = t >> 4;   // rows rg*4 .. rg*4+3
    float acc[4][8];
#pragma unroll
    for (int i = 0; i < 4; i++)
#pragma unroll
        for (int j = 0; j < 8; j++) acc[i][j] = 0.f;

    const float* Arow = As + rg * 4 * 128;
#pragma unroll 8
    for (int k = 0; k < 128; k++) {
        float a[4];
#pragma unroll
        for (int i = 0; i < 4; i++) a[i] = Arow[i * 128 + k];
        float4 b0 = __ldg((const float4*)(B + k * 128 + cq * 8));
        float4 b1 = __ldg((const float4*)(B + k * 128 + cq * 8 + 4));
        float b[8] = {b0.x, b0.y, b0.z, b0.w, b1.x, b1.y, b1.z, b1.w};
#pragma unroll
        for (int i = 0; i < 4; i++)
#pragma unroll
            for (int j = 0; j < 8; j++) acc[i][j] += a[i] * b[j];
    }

#pragma unroll
    for (int i = 0; i < 4; i++) {
        int r = row0 + rg * 4 + i;
        if (r < NROWS) {
            float4* p = reinterpret_cast<float4*>(Out + (size_t)r * 128 + cq * 8);
            p[0] = make_float4(acc[i][0], acc[i][1], acc[i][2], acc[i][3]);
            p[1] = make_float4(acc[i][4], acc[i][5], acc[i][6], acc[i][7]);
        }
    }
}

// ---------------- K2: LDG-direct streaming kernel ----------------
// 2 rows per 256-thread block (independent 128-thread halves, named barriers).
// kf read twice via L1 (cold in phase 1, hits in phase 3); no cp.async/smem tile.
__global__ void __launch_bounds__(256, 5) main_kernel(
    const float* __restrict__ feat, const float* __restrict__ knn_xyz,
    const float* __restrict__ knn_feat, const void* __restrict__ knn_mask,
    float* __restrict__ out_xyz, float* __restrict__ out_att, float* __restrict__ out_ml)
{
    __shared__ float xyzS[2][KNB * 3];
    __shared__ float madjS[2][KNB];
    __shared__ float scS[2][KNB], mlS[2][KNB], attnS[2][KNB];
    __shared__ __align__(16) float pwS[2][4][CDIM];   // per-warp wsum partials
    __shared__ float redS[2][4];

    int tid  = threadIdx.x;
    int h    = tid >> 7;
    int t    = tid & 127;
    int lane = t & 31;
    int w4   = t >> 5;
    int n    = blockIdx.x * 2 + h;

    // small inputs (warp0: mask; warps 0-2: xyz) — consumed only after barriers
    if (t < KNB) {
        bool mv;
        if (g_mask_narrow)
            mv = ((const unsigned char*)knn_mask)[(size_t)n * KNB + t] != 0;
        else
            mv = ((const unsigned int*)knn_mask)[(size_t)n * KNB + t] != 0u;
        madjS[h][t] = mv ? 0.f : -1e12f;
    }
    if (t < KNB * 3) xyzS[h][t] = __ldg(&knn_xyz[(size_t)n * (KNB * 3) + t]);

    // phase 1: dots straight from global (through L1)
    const float4* kf4 = reinterpret_cast<const float4*>(knn_feat + (size_t)n * (KNB * CDIM));
    float4 qv = __ldg(reinterpret_cast<const float4*>(g_qM + (size_t)n * CDIM) + lane);
    float4 fv = __ldg(reinterpret_cast<const float4*>(g_fW + (size_t)n * CDIM) + lane);

    int j0 = w4 * 8;
    float s[8], ml[8];
#pragma unroll
    for (int jj = 0; jj < 8; jj++) {
        float4 k4 = __ldg(kf4 + (j0 + jj) * 32 + lane);
        s [jj] = k4.x * qv.x + k4.y * qv.y + k4.z * qv.z + k4.w * qv.w;
        ml[jj] = k4.x * fv.x + k4.y * fv.y + k4.z * fv.z + k4.w * fv.w;
    }
#pragma unroll
    for (int o = 16; o; o >>= 1) {
#pragma unroll
        for (int jj = 0; jj < 8; jj++) {
            s [jj] += __shfl_xor_sync(0xffffffffu, s [jj], o);
            ml[jj] += __shfl_xor_sync(0xffffffffu, ml[jj], o);
        }
    }
#pragma unroll
    for (int jj = 0; jj < 8; jj++) {
        if (lane == jj) {
            scS[h][j0 + jj] = s[jj];      // raw scores; mask applied by warp 0
            mlS[h][j0 + jj] = ml[jj];
        }
    }
    half_sync(h);

    // phase 2 (warp 0 of half): mask + topk rank + colmask + softmax
    if (t < KNB) {
        float sj = scS[h][t] + madjS[h][t];
        int rank = 0;
#pragma unroll
        for (int i = 0; i < KNB; i++) {
            float si = scS[h][i] + madjS[h][i];
            rank += (si > sj) || (si == sj && i < t);   // lax.top_k stable tie rule
        }
        if (rank < TOPK) {
            if (__ldcg(&g_colmask[t]) == 0) atomicOr(&g_colmask[t], 1);
        }
        g_scores[(size_t)n * KNB + t] = sj;
        out_ml[(size_t)n * KNB + t]   = mlS[h][t];

        float m = sj;
#pragma unroll
        for (int o = 16; o; o >>= 1) m = fmaxf(m, __shfl_xor_sync(0xffffffffu, m, o));
        float e = __expf(sj - m);
        float ssum = e;
#pragma unroll
        for (int o = 16; o; o >>= 1) ssum += __shfl_xor_sync(0xffffffffu, ssum, o);
        attnS[h][t] = e / ssum;
    }
    half_sync(h);

    // phase 3: weighted sum — same addresses as phase 1 (L1 hits), per-warp
    // octet partials, then smem exchange.
    float4 acc4 = make_float4(0.f, 0.f, 0.f, 0.f);
#pragma unroll
    for (int jj = 0; jj < 8; jj++) {
        float  a  = attnS[h][j0 + jj];
        float4 k4 = __ldg(kf4 + (j0 + jj) * 32 + lane);
        acc4.x += a * k4.x; acc4.y += a * k4.y; acc4.z += a * k4.z; acc4.w += a * k4.w;
    }
    *reinterpret_cast<float4*>(&pwS[h][w4][lane * 4]) = acc4;
    half_sync(h);

    float c = pwS[h][0][t] + pwS[h][1][t] + pwS[h][2][t] + pwS[h][3][t];

    size_t ob = (size_t)n * 257;
    out_att[ob + t]       = __ldg(&feat[(size_t)n * CDIM + t]);  // feats[:,0:128]
    out_att[ob + 128 + t] = c;                                   // corres_feat

    float p = __ldg(&g_fW[(size_t)n * CDIM + t]) * c;
#pragma unroll
    for (int o = 16; o; o >>= 1) p += __shfl_xor_sync(0xffffffffu, p, o);
    if (lane == 0) redS[h][w4] = p;
    half_sync(h);
    if (t == 0)
        out_att[ob + 256] = redS[h][0] + redS[h][1] + redS[h][2] + redS[h][3];  // logit

    if (t < 3) {
        float x = 0.f;
#pragma unroll
        for (int j = 0; j < KNB; j++) x += attnS[h][j] * xyzS[h][j * 3 + t];
        out_xyz[(size_t)n * 3 + t] = x;
    }
}

// ---------------- K3: check whether any column never made top-k ----------------
__global__ void check_kernel() {
    int t = threadIdx.x;
    int miss = (t < KNB && g_colmask[t] == 0) ? 1 : 0;
#pragma unroll
    for (int o = 16; o; o >>= 1) miss |= __shfl_xor_sync(0xffffffffu, miss, o);
    if (t == 0) g_needfix = miss;
}

// ---------------- K4: fixup (early-exits when colmask is all-covered) ----------------
__global__ void __launch_bounds__(128) fixup_kernel(
    const float* __restrict__ knn_feat, const float* __restrict__ knn_xyz,
    float* __restrict__ out_xyz, float* __restrict__ out_att)
{
    if (g_needfix == 0) return;   // common case

    __shared__ float attnS[KNB];
    __shared__ float redS[4];
    __shared__ int   colS[KNB];
    int tid = threadIdx.x, lane = tid & 31, warp = tid >> 5;
    if (tid < KNB) colS[tid] = g_colmask[tid];
    __syncthreads();

    for (int n = blockIdx.x; n < NROWS; n += gridDim.x) {
        if (tid < KNB) {
            float s  = g_scores[(size_t)n * KNB + tid];
            int inc  = colS[tid];
            float se = inc ? s : -3.0e38f;
            float m = se;
#pragma unroll
            for (int o = 16; o; o >>= 1) m = fmaxf(m, __shfl_xor_sync(0xffffffffu, m, o));
            float e = inc ? __expf(se - m) : 0.f;
            float ssum = e;
#pragma unroll
            for (int o = 16; o; o >>= 1) ssum += __shfl_xor_sync(0xffffffffu, ssum, o);
            attnS[tid] = e / ssum;
        }
        __syncthreads();

        float acc = 0.f;
#pragma unroll
        for (int j = 0; j < KNB; j++)
            acc += attnS[j] * knn_feat[(size_t)n * (KNB * CDIM) + j * CDIM + tid];

        size_t ob = (size_t)n * 257;
        out_att[ob + 128 + tid] = acc;

        float p = g_fW[(size_t)n * CDIM + tid] * acc;
#pragma unroll
        for (int o = 16; o; o >>= 1) p += __shfl_xor_sync(0xffffffffu, p, o);
        if (lane == 0) redS[warp] = p;
        __syncthreads();
        if (tid == 0) out_att[ob + 256] = redS[0] + redS[1] + redS[2] + redS[3];

        if (tid < 3) {
            float x = 0.f;
#pragma unroll
            for (int j = 0; j < KNB; j++)
                x += attnS[j] * knn_xyz[(size_t)n * (KNB * 3) + j * 3 + tid];
            out_xyz[(size_t)n * 3 + tid] = x;
        }
        __syncthreads();
    }
}

// ---------------- launch ----------------
extern "C" void kernel_launch(void* const* d_in, const int* in_sizes, int n_in,
                              void* d_out, int out_size) {
    const float* feat     = (const float*)d_in[0];          // [N,128]
    const float* knn_xyz  = (const float*)d_in[1];          // [N,32,3]
    const float* knn_feat = (const float*)d_in[2];          // [N,32,128]
    const void*  knn_mask = d_in[3];                        // [N,32] bool (width sniffed)
    const float* Wq       = (const float*)d_in[4];          // [128,128]
    const float* Wk       = (const float*)d_in[5];          // [128,128]
    const float* W        = (const float*)d_in[6];          // [128,128]

    float* out     = (float*)d_out;
    float* out_xyz = out;                                   // [N,3]
    float* out_att = out + (size_t)NROWS * 3;               // [N,257]
    float* out_ml  = out + (size_t)NROWS * 3 + (size_t)NROWS * 257;  // [N,32]

    prep_kernel<<<CDIM, CDIM>>>(Wq, Wk, W);
    sniff_kernel<<<512, 256>>>((const unsigned int*)knn_mask);

    gemm_kernel<<<(NROWS + 63) / 64, 512>>>(feat);

    main_kernel<<<NROWS / 2, 256>>>(feat, knn_xyz, knn_feat, knn_mask,
                                    out_xyz, out_att, out_ml);

    check_kernel<<<1, 32>>>();
    fixup_kernel<<<2048, CDIM>>>(knn_feat, knn_xyz, out_xyz, out_att);
}